// round 12
// baseline (speedup 1.0000x reference)
#include <cuda_runtime.h>

#define NN      100000
#define EEDGES  1600000
#define KIN     128
#define HF      128      // HEADS * OUT_F
#define NHEADS  4

typedef unsigned long long u64;

// ---------------- scratch (static device globals; no allocations) ----------------
__device__ __align__(16) float g_h[(size_t)NN * HF];        // 51.2 MB  h = xW (fp32)
__device__ __align__(16) float g_asrc[NN * NHEADS];
__device__ __align__(16) float g_adst[NN * NHEADS];
__device__ int g_cnt[NN];          // per-dst in-degree (excl self loop)
__device__ int g_off[NN];          // bucket start per dst
__device__ int g_cur[NN];          // scatter cursors
__device__ int g_ss[EEDGES];       // src index of each edge, bucketed by dst
__device__ int g_total;            // global bucket cursor

// ---------------- f32x2 packed-FMA helpers ----------------
__device__ __forceinline__ u64 pack2(float lo, float hi) {
    u64 r; asm("mov.b64 %0, {%1, %2};" : "=l"(r) : "f"(lo), "f"(hi)); return r;
}
__device__ __forceinline__ void ffma2(u64& d, u64 a, u64 b) {
    asm("fma.rn.f32x2 %0, %1, %2, %0;" : "+l"(d) : "l"(a), "l"(b));
}
__device__ __forceinline__ void unpack2(u64 v, float& lo, float& hi) {
    asm("mov.b64 {%0, %1}, %2;" : "=f"(lo), "=f"(hi) : "l"(v));
}

// ---------------- 1. zero per-dst counters + cursor ----------------
__global__ void zero_cnt_kernel(int n) {
    int i = blockIdx.x * blockDim.x + threadIdx.x;
    if (i < n) g_cnt[i] = 0;
    if (i == 0) g_total = 0;
}

// ---------------- 2. GEMM + fused attention-logit epilogue (fp32) ----------------
__global__ __launch_bounds__(256) void gemm_kernel(const float* __restrict__ x,
                                                   const float* __restrict__ W,
                                                   const float* __restrict__ att_src,
                                                   const float* __restrict__ att_dst,
                                                   int n) {
    __shared__ __align__(16) float xs[32][136];
    __shared__ __align__(16) float ws[32][132];
    __shared__ float satt[2][HF];                 // [0]=att_src, [1]=att_dst
    int tid = threadIdx.x;
    int ty = tid >> 4, tx = tid & 15;
    int brow = blockIdx.x * 128;

    if (tid < 128) satt[0][tid] = att_src[tid];
    else           satt[1][tid - 128] = att_dst[tid - 128];

    u64 acc2[2][4][2][2];            // [ri][i][ci][j2]
    #pragma unroll
    for (int a = 0; a < 2; a++)
        #pragma unroll
        for (int b = 0; b < 4; b++)
            #pragma unroll
            for (int c = 0; c < 2; c++)
                #pragma unroll
                for (int d = 0; d < 2; d++) acc2[a][b][c][d] = 0ull;

    for (int kc = 0; kc < 4; kc++) {
        int k0 = kc * 32;
        #pragma unroll
        for (int it = 0; it < 4; it++) {          // x tile (transposed store)
            int f = tid + it * 256;
            int r = f >> 3, kq = f & 7;
            float4 v = make_float4(0.f, 0.f, 0.f, 0.f);
            if (brow + r < n)
                v = *(const float4*)(x + (size_t)(brow + r) * KIN + k0 + kq * 4);
            xs[kq * 4 + 0][r] = v.x; xs[kq * 4 + 1][r] = v.y;
            xs[kq * 4 + 2][r] = v.z; xs[kq * 4 + 3][r] = v.w;
        }
        #pragma unroll
        for (int it = 0; it < 4; it++) {          // W tile
            int f = tid + it * 256;
            int k = f >> 5, c4 = f & 31;
            *(float4*)&ws[k][c4 * 4] =
                *(const float4*)(W + (size_t)(k0 + k) * HF + c4 * 4);
        }
        __syncthreads();

        #pragma unroll
        for (int k = 0; k < 32; k++) {
            float4 a0 = *(float4*)&xs[k][ty * 4];
            float4 a1 = *(float4*)&xs[k][64 + ty * 4];
            float4 b0 = *(float4*)&ws[k][tx * 4];
            float4 b1 = *(float4*)&ws[k][64 + tx * 4];
            u64 bp[2][2] = {{pack2(b0.x, b0.y), pack2(b0.z, b0.w)},
                            {pack2(b1.x, b1.y), pack2(b1.z, b1.w)}};
            float av[2][4] = {{a0.x, a0.y, a0.z, a0.w}, {a1.x, a1.y, a1.z, a1.w}};
            #pragma unroll
            for (int ri = 0; ri < 2; ri++)
                #pragma unroll
                for (int i = 0; i < 4; i++) {
                    u64 ad = pack2(av[ri][i], av[ri][i]);
                    #pragma unroll
                    for (int ci = 0; ci < 2; ci++) {
                        ffma2(acc2[ri][i][ci][0], ad, bp[ci][0]);
                        ffma2(acc2[ri][i][ci][1], ad, bp[ci][1]);
                    }
                }
        }
        __syncthreads();
    }

    // epilogue: store fp32 h rows + fused a_src/a_dst
    #pragma unroll
    for (int ri = 0; ri < 2; ri++)
        #pragma unroll
        for (int i = 0; i < 4; i++) {
            int r = brow + ri * 64 + ty * 4 + i;
            float o[2][4];
            #pragma unroll
            for (int ci = 0; ci < 2; ci++) {
                unpack2(acc2[ri][i][ci][0], o[ci][0], o[ci][1]);
                unpack2(acc2[ri][i][ci][1], o[ci][2], o[ci][3]);
            }
            if (r < n) {
                #pragma unroll
                for (int ci = 0; ci < 2; ci++)
                    *(float4*)(g_h + (size_t)r * HF + ci * 64 + tx * 4) =
                        make_float4(o[ci][0], o[ci][1], o[ci][2], o[ci][3]);
            }
            float ps[2], pd[2];
            #pragma unroll
            for (int ci = 0; ci < 2; ci++) {
                const float* va = &satt[0][ci * 64 + tx * 4];
                const float* vd = &satt[1][ci * 64 + tx * 4];
                ps[ci] = o[ci][0]*va[0] + o[ci][1]*va[1] + o[ci][2]*va[2] + o[ci][3]*va[3];
                pd[ci] = o[ci][0]*vd[0] + o[ci][1]*vd[1] + o[ci][2]*vd[2] + o[ci][3]*vd[3];
            }
            #pragma unroll
            for (int off = 1; off < 8; off <<= 1) {
                #pragma unroll
                for (int ci = 0; ci < 2; ci++) {
                    ps[ci] += __shfl_xor_sync(0xffffffffu, ps[ci], off);
                    pd[ci] += __shfl_xor_sync(0xffffffffu, pd[ci], off);
                }
            }
            if ((tx & 7) == 0 && r < n) {
                int hd = tx >> 3;
                g_asrc[r * 4 + hd]     = ps[0];
                g_asrc[r * 4 + 2 + hd] = ps[1];
                g_adst[r * 4 + hd]     = pd[0];
                g_adst[r * 4 + 2 + hd] = pd[1];
            }
        }
}

// ---------------- 3. histogram of destinations ----------------
__global__ void hist_kernel(const int* __restrict__ ei, int E) {
    int i = blockIdx.x * blockDim.x + threadIdx.x;
    if (i < E) atomicAdd(&g_cnt[ei[E + i]], 1);
}

// ---------------- 4. bucket offsets: block scan + global atomic base ----------------
__global__ __launch_bounds__(1024) void offsets_kernel(int n) {
    __shared__ int wsum[32];
    __shared__ int sbase;
    int tid = threadIdx.x, lane = tid & 31, wid = tid >> 5;
    int i = blockIdx.x * 1024 + tid;
    int v = (i < n) ? g_cnt[i] : 0;
    int incl = v;
    #pragma unroll
    for (int o = 1; o < 32; o <<= 1) {
        int t = __shfl_up_sync(0xffffffffu, incl, o);
        if (lane >= o) incl += t;
    }
    if (lane == 31) wsum[wid] = incl;
    __syncthreads();
    if (wid == 0) {
        int wv = wsum[lane];
        int wincl = wv;
        #pragma unroll
        for (int o = 1; o < 32; o <<= 1) {
            int t = __shfl_up_sync(0xffffffffu, wincl, o);
            if (lane >= o) wincl += t;
        }
        wsum[lane] = wincl - wv;
        if (lane == 31) sbase = atomicAdd(&g_total, wincl);
    }
    __syncthreads();
    int excl = incl - v + wsum[wid] + sbase;
    if (i < n) { g_off[i] = excl; g_cur[i] = excl; }
}

// ---------------- 5. bucket src indices by destination ----------------
__global__ void scatter_kernel(const int* __restrict__ ei, int E) {
    int i = blockIdx.x * blockDim.x + threadIdx.x;
    if (i >= E) return;
    int d = ei[E + i];
    int p = atomicAdd(&g_cur[d], 1);
    g_ss[p] = ei[i];
}

// ---------------- 6. gather/softmax/accumulate: 4 nodes per warp ----------------
// One 8-lane group per node; each lane owns 16 features (4 x float4). 4 groups
// x 4 row-quarter loads per edge = ~16 independent loads in flight per warp.
__global__ __launch_bounds__(256) void agg_kernel(const float* __restrict__ bias,
                                                  float* __restrict__ out, int n) {
    int warp = (blockIdx.x * blockDim.x + threadIdx.x) >> 5;
    int lane = threadIdx.x & 31;
    int g = lane >> 3, l8 = lane & 7;
    int d = warp * 4 + g;
    if (warp * 4 >= n) return;                 // whole warp OOB
    bool nvalid = d < n;
    int dd = nvalid ? d : (n - 1);             // safe node for OOB groups
    int hd = l8 >> 1;                          // head = lane-pair id
    float adst = g_adst[dd * 4 + hd];
    int beg = g_off[dd];
    int cnt = nvalid ? g_cnt[dd] : 0;

    // self loop
    float e0 = g_asrc[dd * 4 + hd] + adst;
    e0 = e0 > 0.f ? e0 : 0.2f * e0;
    float ex0 = __expf(e0);
    float ssum = ex0;
    float4 acc[4];
    {
        const float4* hr = (const float4*)(g_h + (size_t)dd * HF);
        #pragma unroll
        for (int fc = 0; fc < 4; fc++) {
            float4 v = hr[l8 * 4 + fc];
            acc[fc] = make_float4(v.x * ex0, v.y * ex0, v.z * ex0, v.w * ex0);
        }
    }

    // warp-max degree across the 4 groups (groups differ in lane bits 3..4)
    int cntmax = cnt;
    cntmax = max(cntmax, __shfl_xor_sync(0xffffffffu, cntmax, 8));
    cntmax = max(cntmax, __shfl_xor_sync(0xffffffffu, cntmax, 16));

    for (int c0 = 0; c0 < cntmax; c0 += 8) {
        int j = c0 + l8;
        int spre = (j < cnt) ? g_ss[beg + j] : dd;
        int m = cnt - c0;                       // may be <= 0 for this group
        #pragma unroll
        for (int t = 0; t < 8; t++) {
            int s = __shfl_sync(0xffffffffu, spre, (g << 3) + t);
            bool v = t < m;
            if (!v) s = dd;
            float a = g_asrc[s * 4 + hd];
            float e = a + adst;
            e = e > 0.f ? e : 0.2f * e;
            float ex = v ? __expf(e) : 0.f;
            ssum += ex;
            const float4* hr = (const float4*)(g_h + (size_t)s * HF);
            #pragma unroll
            for (int fc = 0; fc < 4; fc++) {
                float4 u = hr[l8 * 4 + fc];
                acc[fc].x += u.x * ex; acc[fc].y += u.y * ex;
                acc[fc].z += u.z * ex; acc[fc].w += u.w * ex;
            }
        }
    }

    if (nvalid) {
        float inv = 1.0f / (ssum + 1e-16f);
        float4* orow = (float4*)(out + (size_t)d * HF);
        #pragma unroll
        for (int fc = 0; fc < 4; fc++) {
            float4 b = ((const float4*)bias)[l8 * 4 + fc];
            orow[l8 * 4 + fc] = make_float4(acc[fc].x * inv + b.x,
                                            acc[fc].y * inv + b.y,
                                            acc[fc].z * inv + b.z,
                                            acc[fc].w * inv + b.w);
        }
    }
}

// ---------------- launch: fork edge-prep onto a side stream ----------------
extern "C" void kernel_launch(void* const* d_in, const int* in_sizes, int n_in,
                              void* d_out, int out_size) {
    const float* x       = (const float*)d_in[0];
    const int*   ei      = (const int*)d_in[1];     // int32 (jax default x64-disabled)
    const float* W       = (const float*)d_in[2];
    const float* att_src = (const float*)d_in[3];
    const float* att_dst = (const float*)d_in[4];
    const float* bias    = (const float*)d_in[5];
    float* out = (float*)d_out;

    int n = in_sizes[0] / KIN;     // 100000
    int E = in_sizes[1] / 2;       // 1600000

    static cudaStream_t s2 = nullptr;
    static cudaEvent_t evFork = nullptr, evJoin = nullptr;
    if (s2 == nullptr) {
        cudaStreamCreateWithFlags(&s2, cudaStreamNonBlocking);
        cudaEventCreateWithFlags(&evFork, cudaEventDisableTiming);
        cudaEventCreateWithFlags(&evJoin, cudaEventDisableTiming);
    }

    // fork: edge-prep chain on s2, GEMM chain on the launch stream
    cudaEventRecord(evFork, 0);
    cudaStreamWaitEvent(s2, evFork, 0);

    zero_cnt_kernel<<<(n + 1023) / 1024, 1024, 0, s2>>>(n);
    hist_kernel<<<(E + 255) / 256, 256, 0, s2>>>(ei, E);
    offsets_kernel<<<(n + 1023) / 1024, 1024, 0, s2>>>(n);
    scatter_kernel<<<(E + 255) / 256, 256, 0, s2>>>(ei, E);
    cudaEventRecord(evJoin, s2);

    gemm_kernel<<<(n + 127) / 128, 256>>>(x, W, att_src, att_dst, n);

    // join, then aggregate
    cudaStreamWaitEvent(0, evJoin, 0);
    {
        int nwarps = (n + 3) / 4;                       // 4 nodes per warp
        long long threads = (long long)nwarps * 32;
        int blocks = (int)((threads + 255) / 256);
        agg_kernel<<<blocks, 256>>>(bias, out, n);
    }
}

// round 13
// speedup vs baseline: 1.4124x; 1.4124x over previous
#include <cuda_runtime.h>

#define NN      100000
#define EEDGES  1600000
#define KIN     128
#define HF      128      // HEADS * OUT_F
#define NHEADS  4

typedef unsigned long long u64;

// ---------------- scratch (static device globals; no allocations) ----------------
__device__ __align__(16) float g_h[(size_t)NN * HF];        // 51.2 MB  h = xW (fp32)
__device__ __align__(16) float g_asrc[NN * NHEADS];
__device__ __align__(16) float g_adst[NN * NHEADS];
__device__ int g_cnt[NN];          // per-dst in-degree (excl self loop)
__device__ int g_off[NN];          // bucket start per dst
__device__ int g_cur[NN];          // scatter cursors
__device__ int g_ss[EEDGES];       // src index of each edge, bucketed by dst
__device__ int g_total;            // global bucket cursor

// ---------------- f32x2 packed-FMA helpers ----------------
__device__ __forceinline__ u64 pack2(float lo, float hi) {
    u64 r; asm("mov.b64 %0, {%1, %2};" : "=l"(r) : "f"(lo), "f"(hi)); return r;
}
__device__ __forceinline__ void ffma2(u64& d, u64 a, u64 b) {
    asm("fma.rn.f32x2 %0, %1, %2, %0;" : "+l"(d) : "l"(a), "l"(b));
}
__device__ __forceinline__ void unpack2(u64 v, float& lo, float& hi) {
    asm("mov.b64 {%0, %1}, %2;" : "=f"(lo), "=f"(hi) : "l"(v));
}

// ---------------- 1. zero per-dst counters + cursor ----------------
__global__ void zero_cnt_kernel(int n) {
    int i = blockIdx.x * blockDim.x + threadIdx.x;
    if (i < n) g_cnt[i] = 0;
    if (i == 0) g_total = 0;
}

// ---------------- 2. GEMM + fused attention-logit epilogue (fp32) ----------------
__global__ __launch_bounds__(256) void gemm_kernel(const float* __restrict__ x,
                                                   const float* __restrict__ W,
                                                   const float* __restrict__ att_src,
                                                   const float* __restrict__ att_dst,
                                                   int n) {
    __shared__ __align__(16) float xs[32][136];
    __shared__ __align__(16) float ws[32][132];
    __shared__ float satt[2][HF];                 // [0]=att_src, [1]=att_dst
    int tid = threadIdx.x;
    int ty = tid >> 4, tx = tid & 15;
    int brow = blockIdx.x * 128;

    if (tid < 128) satt[0][tid] = att_src[tid];
    else           satt[1][tid - 128] = att_dst[tid - 128];

    u64 acc2[2][4][2][2];            // [ri][i][ci][j2]
    #pragma unroll
    for (int a = 0; a < 2; a++)
        #pragma unroll
        for (int b = 0; b < 4; b++)
            #pragma unroll
            for (int c = 0; c < 2; c++)
                #pragma unroll
                for (int d = 0; d < 2; d++) acc2[a][b][c][d] = 0ull;

    for (int kc = 0; kc < 4; kc++) {
        int k0 = kc * 32;
        #pragma unroll
        for (int it = 0; it < 4; it++) {          // x tile (transposed store)
            int f = tid + it * 256;
            int r = f >> 3, kq = f & 7;
            float4 v = make_float4(0.f, 0.f, 0.f, 0.f);
            if (brow + r < n)
                v = *(const float4*)(x + (size_t)(brow + r) * KIN + k0 + kq * 4);
            xs[kq * 4 + 0][r] = v.x; xs[kq * 4 + 1][r] = v.y;
            xs[kq * 4 + 2][r] = v.z; xs[kq * 4 + 3][r] = v.w;
        }
        #pragma unroll
        for (int it = 0; it < 4; it++) {          // W tile
            int f = tid + it * 256;
            int k = f >> 5, c4 = f & 31;
            *(float4*)&ws[k][c4 * 4] =
                *(const float4*)(W + (size_t)(k0 + k) * HF + c4 * 4);
        }
        __syncthreads();

        #pragma unroll
        for (int k = 0; k < 32; k++) {
            float4 a0 = *(float4*)&xs[k][ty * 4];
            float4 a1 = *(float4*)&xs[k][64 + ty * 4];
            float4 b0 = *(float4*)&ws[k][tx * 4];
            float4 b1 = *(float4*)&ws[k][64 + tx * 4];
            u64 bp[2][2] = {{pack2(b0.x, b0.y), pack2(b0.z, b0.w)},
                            {pack2(b1.x, b1.y), pack2(b1.z, b1.w)}};
            float av[2][4] = {{a0.x, a0.y, a0.z, a0.w}, {a1.x, a1.y, a1.z, a1.w}};
            #pragma unroll
            for (int ri = 0; ri < 2; ri++)
                #pragma unroll
                for (int i = 0; i < 4; i++) {
                    u64 ad = pack2(av[ri][i], av[ri][i]);
                    #pragma unroll
                    for (int ci = 0; ci < 2; ci++) {
                        ffma2(acc2[ri][i][ci][0], ad, bp[ci][0]);
                        ffma2(acc2[ri][i][ci][1], ad, bp[ci][1]);
                    }
                }
        }
        __syncthreads();
    }

    // epilogue: store fp32 h rows + fused a_src/a_dst
    #pragma unroll
    for (int ri = 0; ri < 2; ri++)
        #pragma unroll
        for (int i = 0; i < 4; i++) {
            int r = brow + ri * 64 + ty * 4 + i;
            float o[2][4];
            #pragma unroll
            for (int ci = 0; ci < 2; ci++) {
                unpack2(acc2[ri][i][ci][0], o[ci][0], o[ci][1]);
                unpack2(acc2[ri][i][ci][1], o[ci][2], o[ci][3]);
            }
            if (r < n) {
                #pragma unroll
                for (int ci = 0; ci < 2; ci++)
                    *(float4*)(g_h + (size_t)r * HF + ci * 64 + tx * 4) =
                        make_float4(o[ci][0], o[ci][1], o[ci][2], o[ci][3]);
            }
            float ps[2], pd[2];
            #pragma unroll
            for (int ci = 0; ci < 2; ci++) {
                const float* va = &satt[0][ci * 64 + tx * 4];
                const float* vd = &satt[1][ci * 64 + tx * 4];
                ps[ci] = o[ci][0]*va[0] + o[ci][1]*va[1] + o[ci][2]*va[2] + o[ci][3]*va[3];
                pd[ci] = o[ci][0]*vd[0] + o[ci][1]*vd[1] + o[ci][2]*vd[2] + o[ci][3]*vd[3];
            }
            #pragma unroll
            for (int off = 1; off < 8; off <<= 1) {
                #pragma unroll
                for (int ci = 0; ci < 2; ci++) {
                    ps[ci] += __shfl_xor_sync(0xffffffffu, ps[ci], off);
                    pd[ci] += __shfl_xor_sync(0xffffffffu, pd[ci], off);
                }
            }
            if ((tx & 7) == 0 && r < n) {
                int hd = tx >> 3;
                g_asrc[r * 4 + hd]     = ps[0];
                g_asrc[r * 4 + 2 + hd] = ps[1];
                g_adst[r * 4 + hd]     = pd[0];
                g_adst[r * 4 + 2 + hd] = pd[1];
            }
        }
}

// ---------------- 3. histogram of destinations ----------------
__global__ void hist_kernel(const int* __restrict__ ei, int E) {
    int i = blockIdx.x * blockDim.x + threadIdx.x;
    if (i < E) atomicAdd(&g_cnt[ei[E + i]], 1);
}

// ---------------- 4. bucket offsets: block scan + global atomic base ----------------
__global__ __launch_bounds__(1024) void offsets_kernel(int n) {
    __shared__ int wsum[32];
    __shared__ int sbase;
    int tid = threadIdx.x, lane = tid & 31, wid = tid >> 5;
    int i = blockIdx.x * 1024 + tid;
    int v = (i < n) ? g_cnt[i] : 0;
    int incl = v;
    #pragma unroll
    for (int o = 1; o < 32; o <<= 1) {
        int t = __shfl_up_sync(0xffffffffu, incl, o);
        if (lane >= o) incl += t;
    }
    if (lane == 31) wsum[wid] = incl;
    __syncthreads();
    if (wid == 0) {
        int wv = wsum[lane];
        int wincl = wv;
        #pragma unroll
        for (int o = 1; o < 32; o <<= 1) {
            int t = __shfl_up_sync(0xffffffffu, wincl, o);
            if (lane >= o) wincl += t;
        }
        wsum[lane] = wincl - wv;
        if (lane == 31) sbase = atomicAdd(&g_total, wincl);
    }
    __syncthreads();
    int excl = incl - v + wsum[wid] + sbase;
    if (i < n) { g_off[i] = excl; g_cur[i] = excl; }
}

// ---------------- 5. bucket src indices by destination ----------------
__global__ void scatter_kernel(const int* __restrict__ ei, int E) {
    int i = blockIdx.x * blockDim.x + threadIdx.x;
    if (i >= E) return;
    int d = ei[E + i];
    int p = atomicAdd(&g_cur[d], 1);
    g_ss[p] = ei[i];
}

// ---------------- 6. gather/softmax/accumulate (warp per node, batch-8 pipeline) ----------------
// Explicit 8-deep batches: shfl all indices, issue all loads, then consume.
__global__ __launch_bounds__(256) void agg_kernel(const float* __restrict__ bias,
                                                  float* __restrict__ out, int n) {
    int w = (blockIdx.x * blockDim.x + threadIdx.x) >> 5;
    int lane = threadIdx.x & 31;
    if (w >= n) return;
    int d = w;
    int hd = lane >> 3;
    float adst = g_adst[d * 4 + hd];
    int beg = g_off[d], cnt = g_cnt[d];

    // self loop
    float e0 = g_asrc[d * 4 + hd] + adst;
    e0 = e0 > 0.f ? e0 : 0.2f * e0;
    float ex0 = __expf(e0);
    float ssum = ex0;
    float4 acc;
    {
        float4 hv = *(const float4*)(g_h + (size_t)d * HF + lane * 4);
        acc = make_float4(hv.x * ex0, hv.y * ex0, hv.z * ex0, hv.w * ex0);
    }

    for (int c0 = 0; c0 < cnt; c0 += 32) {
        int j = c0 + lane;
        int spre = (j < cnt) ? g_ss[beg + j] : 0;
        int m = cnt - c0; if (m > 32) m = 32;
        for (int t0 = 0; t0 < m; t0 += 8) {
            int kk = m - t0; if (kk > 8) kk = 8;
            // phase 1: broadcast 8 indices (independent shfls)
            int sarr[8];
            #pragma unroll
            for (int t = 0; t < 8; t++) {
                int s = __shfl_sync(0xffffffffu, spre, t0 + t);
                sarr[t] = (t < kk) ? s : d;        // safe row for tail
            }
            // phase 2: issue all loads back-to-back (MLP = 8)
            float  aarr[8];
            float4 harr[8];
            #pragma unroll
            for (int t = 0; t < 8; t++) {
                aarr[t] = g_asrc[sarr[t] * 4 + hd];
                harr[t] = *(const float4*)(g_h + (size_t)sarr[t] * HF + lane * 4);
            }
            // phase 3: consume
            #pragma unroll
            for (int t = 0; t < 8; t++) {
                float e = aarr[t] + adst;
                e = e > 0.f ? e : 0.2f * e;
                float ex = (t < kk) ? __expf(e) : 0.f;
                ssum += ex;
                acc.x += harr[t].x * ex; acc.y += harr[t].y * ex;
                acc.z += harr[t].z * ex; acc.w += harr[t].w * ex;
            }
        }
    }

    float inv = 1.0f / (ssum + 1e-16f);
    float4 b = *(const float4*)(bias + lane * 4);
    float4 o = make_float4(acc.x * inv + b.x, acc.y * inv + b.y,
                           acc.z * inv + b.z, acc.w * inv + b.w);
    *(float4*)(out + (size_t)d * HF + lane * 4) = o;
}

// ---------------- launch: fork edge-prep onto a side stream ----------------
extern "C" void kernel_launch(void* const* d_in, const int* in_sizes, int n_in,
                              void* d_out, int out_size) {
    const float* x       = (const float*)d_in[0];
    const int*   ei      = (const int*)d_in[1];     // int32 (jax default x64-disabled)
    const float* W       = (const float*)d_in[2];
    const float* att_src = (const float*)d_in[3];
    const float* att_dst = (const float*)d_in[4];
    const float* bias    = (const float*)d_in[5];
    float* out = (float*)d_out;

    int n = in_sizes[0] / KIN;     // 100000
    int E = in_sizes[1] / 2;       // 1600000

    static cudaStream_t s2 = nullptr;
    static cudaEvent_t evFork = nullptr, evJoin = nullptr;
    if (s2 == nullptr) {
        cudaStreamCreateWithFlags(&s2, cudaStreamNonBlocking);
        cudaEventCreateWithFlags(&evFork, cudaEventDisableTiming);
        cudaEventCreateWithFlags(&evJoin, cudaEventDisableTiming);
    }

    // fork: edge-prep chain on s2, GEMM chain on the launch stream
    cudaEventRecord(evFork, 0);
    cudaStreamWaitEvent(s2, evFork, 0);

    zero_cnt_kernel<<<(n + 1023) / 1024, 1024, 0, s2>>>(n);
    hist_kernel<<<(E + 255) / 256, 256, 0, s2>>>(ei, E);
    offsets_kernel<<<(n + 1023) / 1024, 1024, 0, s2>>>(n);
    scatter_kernel<<<(E + 255) / 256, 256, 0, s2>>>(ei, E);
    cudaEventRecord(evJoin, s2);

    gemm_kernel<<<(n + 127) / 128, 256>>>(x, W, att_src, att_dst, n);

    // join, then aggregate
    cudaStreamWaitEvent(0, evJoin, 0);
    {
        long long threads = (long long)n * 32;
        int blocks = (int)((threads + 255) / 256);
        agg_kernel<<<blocks, 256>>>(bias, out, n);
    }
}